// round 5
// baseline (speedup 1.0000x reference)
#include <cuda_runtime.h>
#include <cuda_bf16.h>
#include <math.h>

#define NUM_LAYERS 2
#define B_SZ 2
#define S_TOTAL 13294
#define D_MODEL 256
#define NH 8
#define DH 32
#define NL 4
#define NP 4
#define DFF 1024
#define M_TOTAL (B_SZ * S_TOTAL)

__constant__ int c_H[4]     = {100, 50, 25, 13};
__constant__ int c_W[4]     = {100, 50, 25, 13};
__constant__ int c_start[4] = {0, 10000, 12500, 13125};

// ---------------- scratch (static device globals; no allocation) -------------
__device__ float g_value[M_TOTAL * D_MODEL];
__device__ float g_off  [M_TOTAL * D_MODEL];
__device__ float g_attn [M_TOTAL * 128];
__device__ float g_msda [M_TOTAL * D_MODEL];
__device__ float g_tmp  [M_TOTAL * D_MODEL];
__device__ float g_x    [M_TOTAL * D_MODEL];
__device__ float g_hid  [M_TOTAL * DFF];
__device__ float g_ref  [M_TOTAL * NL * 2];

// ---------------- reference points ------------------------------------------
__global__ void ref_kernel(const float* __restrict__ vr, float* __restrict__ ref)
{
    int idx = blockIdx.x * blockDim.x + threadIdx.x;
    if (idx >= B_SZ * S_TOTAL) return;
    int b = idx / S_TOTAL;
    int s = idx % S_TOTAL;

    int lvl = 0, rem = s;
    while (lvl < 3 && rem >= c_H[lvl] * c_W[lvl]) { rem -= c_H[lvl] * c_W[lvl]; lvl++; }
    int W_ = c_W[lvl], H_ = c_H[lvl];
    int i = rem / W_, j = rem % W_;

    float vrx = vr[(b * NL + lvl) * 2 + 0];
    float vry = vr[(b * NL + lvl) * 2 + 1];
    float bx = (j + 0.5f) / (vrx * (float)W_);
    float by = (i + 0.5f) / (vry * (float)H_);

    #pragma unroll
    for (int l = 0; l < NL; l++) {
        float vx = vr[(b * NL + l) * 2 + 0];
        float vy = vr[(b * NL + l) * 2 + 1];
        ref[((size_t)idx * NL + l) * 2 + 0] = bx * vx;
        ref[((size_t)idx * NL + l) * 2 + 1] = by * vy;
    }
}

// ---------------- TF32 tensor-core GEMM --------------------------------------
__device__ __forceinline__ unsigned f2tf32(float f) {
    unsigned u;
    asm("cvt.rna.tf32.f32 %0, %1;" : "=r"(u) : "f"(f));
    return u;
}

#define MMA_TF32(c0,c1,c2,c3, a0,a1,a2,a3, b0,b1) \
    asm volatile("mma.sync.aligned.m16n8k8.row.col.f32.tf32.tf32.f32 " \
        "{%0,%1,%2,%3},{%4,%5,%6,%7},{%8,%9},{%0,%1,%2,%3};" \
        : "+f"(c0), "+f"(c1), "+f"(c2), "+f"(c3) \
        : "r"(a0), "r"(a1), "r"(a2), "r"(a3), "r"(b0), "r"(b1))

#define LDK 136

__global__ __launch_bounds__(256)
void gemm_tc_kernel(const float* __restrict__ A,
                    const float* __restrict__ W,
                    const float* __restrict__ bias,
                    float* __restrict__ C,
                    int M, int N, int K, int doRelu)
{
    __shared__ unsigned As[2][16][LDK];   // [buf][k][m]
    __shared__ unsigned Bs[2][16][LDK];   // [buf][k][n]

    const int bm = blockIdx.y * 128;
    const int bn = blockIdx.x * 128;
    const int tid  = threadIdx.x;
    const int lane = tid & 31;
    const int warp = tid >> 5;
    const int wm = (warp >> 2) * 64;   // 0 / 64
    const int wn = (warp & 3) * 32;    // 0..96

    const int arow = tid >> 1;          // 0..127
    const int acol = (tid & 1) * 8;     // 0 / 8
    const int brow = tid >> 4;          // 0..15
    const int bcol = (tid & 15) * 8;    // 0..120

    const int grow = lane >> 2;   // 0..7
    const int gk   = lane & 3;    // 0..3

    float c[4][4][4];
    #pragma unroll
    for (int i = 0; i < 4; i++)
        #pragma unroll
        for (int j = 0; j < 4; j++)
            #pragma unroll
            for (int r = 0; r < 4; r++) c[i][j][r] = 0.f;

    const int NT = K >> 4;
    float4 pa0, pa1, pb0, pb1;
    const bool arow_ok = (bm + arow < M);

    {
        pa0 = make_float4(0.f,0.f,0.f,0.f); pa1 = pa0;
        if (arow_ok) {
            const float* ap = A + (size_t)(bm + arow) * K + acol;
            pa0 = *(const float4*)ap;
            pa1 = *(const float4*)(ap + 4);
        }
        pb0 = *(const float4*)(W + (size_t)brow * N + bn + bcol);
        pb1 = *(const float4*)(W + (size_t)brow * N + bn + bcol + 4);

        As[0][acol+0][arow] = f2tf32(pa0.x); As[0][acol+1][arow] = f2tf32(pa0.y);
        As[0][acol+2][arow] = f2tf32(pa0.z); As[0][acol+3][arow] = f2tf32(pa0.w);
        As[0][acol+4][arow] = f2tf32(pa1.x); As[0][acol+5][arow] = f2tf32(pa1.y);
        As[0][acol+6][arow] = f2tf32(pa1.z); As[0][acol+7][arow] = f2tf32(pa1.w);
        uint4 u0 = make_uint4(f2tf32(pb0.x), f2tf32(pb0.y), f2tf32(pb0.z), f2tf32(pb0.w));
        uint4 u1 = make_uint4(f2tf32(pb1.x), f2tf32(pb1.y), f2tf32(pb1.z), f2tf32(pb1.w));
        *(uint4*)&Bs[0][brow][bcol]     = u0;
        *(uint4*)&Bs[0][brow][bcol + 4] = u1;
    }
    __syncthreads();

    for (int t = 0; t < NT; t++) {
        const int cur = t & 1;
        const int nxt = cur ^ 1;

        if (t + 1 < NT) {
            const int k0 = (t + 1) << 4;
            pa0 = make_float4(0.f,0.f,0.f,0.f); pa1 = pa0;
            if (arow_ok) {
                const float* ap = A + (size_t)(bm + arow) * K + k0 + acol;
                pa0 = *(const float4*)ap;
                pa1 = *(const float4*)(ap + 4);
            }
            pb0 = *(const float4*)(W + (size_t)(k0 + brow) * N + bn + bcol);
            pb1 = *(const float4*)(W + (size_t)(k0 + brow) * N + bn + bcol + 4);
        }

        #pragma unroll
        for (int ks = 0; ks < 2; ks++) {
            const int kb = ks * 8;
            unsigned af[4][4], bf[4][2];
            #pragma unroll
            for (int mt = 0; mt < 4; mt++) {
                int r = wm + mt * 16 + grow;
                af[mt][0] = As[cur][kb + gk    ][r];
                af[mt][1] = As[cur][kb + gk    ][r + 8];
                af[mt][2] = As[cur][kb + gk + 4][r];
                af[mt][3] = As[cur][kb + gk + 4][r + 8];
            }
            #pragma unroll
            for (int nt = 0; nt < 4; nt++) {
                int n = wn + nt * 8 + grow;
                bf[nt][0] = Bs[cur][kb + gk    ][n];
                bf[nt][1] = Bs[cur][kb + gk + 4][n];
            }
            #pragma unroll
            for (int mt = 0; mt < 4; mt++)
                #pragma unroll
                for (int nt = 0; nt < 4; nt++)
                    MMA_TF32(c[mt][nt][0], c[mt][nt][1], c[mt][nt][2], c[mt][nt][3],
                             af[mt][0], af[mt][1], af[mt][2], af[mt][3],
                             bf[nt][0], bf[nt][1]);
        }

        if (t + 1 < NT) {
            As[nxt][acol+0][arow] = f2tf32(pa0.x); As[nxt][acol+1][arow] = f2tf32(pa0.y);
            As[nxt][acol+2][arow] = f2tf32(pa0.z); As[nxt][acol+3][arow] = f2tf32(pa0.w);
            As[nxt][acol+4][arow] = f2tf32(pa1.x); As[nxt][acol+5][arow] = f2tf32(pa1.y);
            As[nxt][acol+6][arow] = f2tf32(pa1.z); As[nxt][acol+7][arow] = f2tf32(pa1.w);
            uint4 u0 = make_uint4(f2tf32(pb0.x), f2tf32(pb0.y), f2tf32(pb0.z), f2tf32(pb0.w));
            uint4 u1 = make_uint4(f2tf32(pb1.x), f2tf32(pb1.y), f2tf32(pb1.z), f2tf32(pb1.w));
            *(uint4*)&Bs[nxt][brow][bcol]     = u0;
            *(uint4*)&Bs[nxt][brow][bcol + 4] = u1;
        }
        __syncthreads();
    }

    #pragma unroll
    for (int mt = 0; mt < 4; mt++) {
        int row0 = bm + wm + mt * 16 + grow;
        #pragma unroll
        for (int nt = 0; nt < 4; nt++) {
            int gn = bn + wn + nt * 8 + (lane & 3) * 2;
            float b0 = bias[gn], b1 = bias[gn + 1];
            if (row0 < M) {
                float v0 = c[mt][nt][0] + b0;
                float v1 = c[mt][nt][1] + b1;
                if (doRelu) { v0 = fmaxf(v0, 0.f); v1 = fmaxf(v1, 0.f); }
                *(float2*)(C + (size_t)row0 * N + gn) = make_float2(v0, v1);
            }
            if (row0 + 8 < M) {
                float v2 = c[mt][nt][2] + b0;
                float v3 = c[mt][nt][3] + b1;
                if (doRelu) { v2 = fmaxf(v2, 0.f); v3 = fmaxf(v3, 0.f); }
                *(float2*)(C + (size_t)(row0 + 8) * N + gn) = make_float2(v2, v3);
            }
        }
    }
}

// ---------------- MSDA v2: branch-free bilinear, shuffled offsets ------------
// one warp per (b, q, head); lane = channel
__global__ __launch_bounds__(256)
void msda_kernel(const float* __restrict__ value,
                 const float* __restrict__ off,
                 const float* __restrict__ attn_logits,
                 const float* __restrict__ ref,
                 float* __restrict__ out)
{
    constexpr int kH[4]  = {100, 50, 25, 13};
    constexpr int kW[4]  = {100, 50, 25, 13};
    constexpr int kSt[4] = {0, 10000, 12500, 13125};

    int gwarp = (blockIdx.x * blockDim.x + threadIdx.x) >> 5;
    int lane  = threadIdx.x & 31;
    if (gwarp >= B_SZ * S_TOTAL * NH) return;

    int h  = gwarp & (NH - 1);
    int bq = gwarp >> 3;            // b*S + q
    int b  = (bq >= S_TOTAL) ? 1 : 0;

    // one coalesced load of all 32 offsets for this (bq, head): [NL][NP][2]
    float offv = __ldg(off + (size_t)bq * 256 + h * 32 + lane);

    // softmax over 16 sampling logits (lanes 0..15 hold them)
    const float* lg = attn_logits + (size_t)bq * 128 + h * 16;
    float v = (lane < 16) ? __ldg(lg + lane) : -1e30f;
    float m = v;
    #pragma unroll
    for (int o = 16; o > 0; o >>= 1) m = fmaxf(m, __shfl_xor_sync(0xffffffffu, m, o));
    float e = (lane < 16) ? __expf(v - m) : 0.f;
    float ssum = e;
    #pragma unroll
    for (int o = 16; o > 0; o >>= 1) ssum += __shfl_xor_sync(0xffffffffu, ssum, o);
    float aw = e / ssum;   // lane's attention weight for sample index == lane

    const float* refp = ref + (size_t)bq * (NL * 2);

    float acc = 0.f;
    #pragma unroll
    for (int l = 0; l < NL; l++) {
        const int H_ = kH[l], W_ = kW[l];
        const float fW = (float)W_, fH = (float)H_;
        const float invW = 1.f / fW, invH = 1.f / fH;
        float refx = __ldg(refp + l * 2 + 0);
        float refy = __ldg(refp + l * 2 + 1);
        const float* vbase = value + ((size_t)(b * S_TOTAL + kSt[l]) * NH + h) * DH + lane;

        #pragma unroll
        for (int p = 0; p < NP; p++) {
            const int idx16 = l * NP + p;
            float w16 = __shfl_sync(0xffffffffu, aw, idx16);
            float ox  = __shfl_sync(0xffffffffu, offv, 2 * idx16);
            float oy  = __shfl_sync(0xffffffffu, offv, 2 * idx16 + 1);

            float x = (refx + ox * invW) * fW - 0.5f;
            float y = (refy + oy * invH) * fH - 0.5f;
            float x0f = floorf(x), y0f = floorf(y);
            int x0 = (int)x0f, y0 = (int)y0f;
            float fx = x - x0f, fy = y - y0f;

            // validity masks folded into weights (branch-free)
            float mx0 = ((unsigned)x0     < (unsigned)W_) ? 1.f : 0.f;
            float mx1 = ((unsigned)(x0+1) < (unsigned)W_) ? 1.f : 0.f;
            float my0 = ((unsigned)y0     < (unsigned)H_) ? 1.f : 0.f;
            float my1 = ((unsigned)(y0+1) < (unsigned)H_) ? 1.f : 0.f;

            float gx1 = fx * mx1, gx0 = (1.f - fx) * mx0;
            float gy1 = fy * my1, gy0 = (1.f - fy) * my0;
            float w00 = gx0 * gy0, w10 = gx1 * gy0;
            float w01 = gx0 * gy1, w11 = gx1 * gy1;

            int cx0 = min(max(x0, 0), W_ - 1);
            int cx1 = min(max(x0 + 1, 0), W_ - 1);
            int cy0 = min(max(y0, 0), H_ - 1);
            int cy1 = min(max(y0 + 1, 0), H_ - 1);
            int r0 = cy0 * W_, r1 = cy1 * W_;

            float v00 = __ldg(vbase + (r0 + cx0) * (NH * DH));
            float v10 = __ldg(vbase + (r0 + cx1) * (NH * DH));
            float v01 = __ldg(vbase + (r1 + cx0) * (NH * DH));
            float v11 = __ldg(vbase + (r1 + cx1) * (NH * DH));

            float s = fmaf(w00, v00, fmaf(w10, v10, fmaf(w01, v01, w11 * v11)));
            acc = fmaf(w16, s, acc);
        }
    }
    out[((size_t)bq * NH + h) * DH + lane] = acc;
}

// ---------------- residual add + LayerNorm (one block per row, 256 thr) -----
__global__ void add_ln_kernel(const float* __restrict__ xin,
                              const float* __restrict__ r,
                              const float* __restrict__ g,
                              const float* __restrict__ bt,
                              float* __restrict__ xout)
{
    int row = blockIdx.x;
    int t = threadIdx.x;
    float v = xin[(size_t)row * 256 + t] + r[(size_t)row * 256 + t];

    float s1 = v, s2 = v * v;
    #pragma unroll
    for (int o = 16; o > 0; o >>= 1) {
        s1 += __shfl_xor_sync(0xffffffffu, s1, o);
        s2 += __shfl_xor_sync(0xffffffffu, s2, o);
    }
    __shared__ float sh1[8], sh2[8];
    int w = t >> 5, lane = t & 31;
    if (lane == 0) { sh1[w] = s1; sh2[w] = s2; }
    __syncthreads();
    if (w == 0) {
        s1 = (lane < 8) ? sh1[lane] : 0.f;
        s2 = (lane < 8) ? sh2[lane] : 0.f;
        #pragma unroll
        for (int o = 4; o > 0; o >>= 1) {
            s1 += __shfl_xor_sync(0xffffffffu, s1, o);
            s2 += __shfl_xor_sync(0xffffffffu, s2, o);
        }
        if (lane == 0) { sh1[0] = s1; sh2[0] = s2; }
    }
    __syncthreads();
    float mean = sh1[0] * (1.f / 256.f);
    float var  = sh2[0] * (1.f / 256.f) - mean * mean;
    float inv  = rsqrtf(var + 1e-5f);
    xout[(size_t)row * 256 + t] = (v - mean) * inv * g[t] + bt[t];
}

// -----------------------------------------------------------------------------
extern "C" void kernel_launch(void* const* d_in, const int* in_sizes, int n_in,
                              void* d_out, int out_size)
{
    const float* src    = (const float*)d_in[0];
    const float* vr     = (const float*)d_in[2];
    const float* W_off  = (const float*)d_in[3];
    const float* b_off  = (const float*)d_in[4];
    const float* W_attn = (const float*)d_in[5];
    const float* b_attn = (const float*)d_in[6];
    const float* W_val  = (const float*)d_in[7];
    const float* b_val  = (const float*)d_in[8];
    const float* W_out  = (const float*)d_in[9];
    const float* b_out  = (const float*)d_in[10];
    const float* ln1_g  = (const float*)d_in[11];
    const float* ln1_b  = (const float*)d_in[12];
    const float* W1     = (const float*)d_in[13];
    const float* b1     = (const float*)d_in[14];
    const float* W2     = (const float*)d_in[15];
    const float* b2     = (const float*)d_in[16];
    const float* ln2_g  = (const float*)d_in[17];
    const float* ln2_b  = (const float*)d_in[18];

    float *value, *off, *attn, *msda, *tmp, *xb, *hid, *refp;
    cudaGetSymbolAddress((void**)&value, g_value);
    cudaGetSymbolAddress((void**)&off,   g_off);
    cudaGetSymbolAddress((void**)&attn,  g_attn);
    cudaGetSymbolAddress((void**)&msda,  g_msda);
    cudaGetSymbolAddress((void**)&tmp,   g_tmp);
    cudaGetSymbolAddress((void**)&xb,    g_x);
    cudaGetSymbolAddress((void**)&hid,   g_hid);
    cudaGetSymbolAddress((void**)&refp,  g_ref);

    const int M = M_TOTAL;
    const int GM = (M + 127) / 128;   // 208

    ref_kernel<<<(M + 255) / 256, 256>>>(vr, refp);

    for (int i = 0; i < NUM_LAYERS; i++) {
        const float* xin = (i == 0) ? src : xb;

        gemm_tc_kernel<<<dim3(2, GM), 256>>>(xin, W_val + (size_t)i * 256 * 256,
                                             b_val + i * 256, value, M, 256, 256, 0);
        gemm_tc_kernel<<<dim3(2, GM), 256>>>(xin, W_off + (size_t)i * 256 * 256,
                                             b_off + i * 256, off, M, 256, 256, 0);
        gemm_tc_kernel<<<dim3(1, GM), 256>>>(xin, W_attn + (size_t)i * 256 * 128,
                                             b_attn + i * 128, attn, M, 128, 256, 0);

        int nwarps = B_SZ * S_TOTAL * NH;
        msda_kernel<<<(nwarps * 32 + 255) / 256, 256>>>(value, off, attn, refp, msda);

        gemm_tc_kernel<<<dim3(2, GM), 256>>>(msda, W_out + (size_t)i * 256 * 256,
                                             b_out + i * 256, tmp, M, 256, 256, 0);
        add_ln_kernel<<<M, 256>>>(xin, tmp, ln1_g + i * 256, ln1_b + i * 256, xb);

        gemm_tc_kernel<<<dim3(8, GM), 256>>>(xb, W1 + (size_t)i * 256 * 1024,
                                             b1 + i * 1024, hid, M, 1024, 256, 1);
        gemm_tc_kernel<<<dim3(2, GM), 256>>>(hid, W2 + (size_t)i * 1024 * 256,
                                             b2 + i * 256, tmp, M, 256, 1024, 0);

        float* lnout = (i == NUM_LAYERS - 1) ? (float*)d_out : xb;
        add_ln_kernel<<<M, 256>>>(xb, tmp, ln2_g + i * 256, ln2_b + i * 256, lnout);
    }
}